// round 13
// baseline (speedup 1.0000x reference)
#include <cuda_runtime.h>
#include <cuda_bf16.h>

#define BB     16
#define NN     4096
#define SS     1024
#define NS     32
#define MM     (BB*SS*NS)
#define EPSF   1e-5

__device__ __align__(16) float  g_ppre[(size_t)BB*NN*64];
__device__ __align__(16) float  g_y0[(size_t)MM*64];
__device__ __align__(16) float  g_y1[(size_t)MM*64];
__device__ __align__(16) float4 g_pts4[(size_t)BB*NN];
__device__ __align__(16) float4 g_c4[BB*SS];
__device__           float g_part[8192*2*128];
__device__           float g_dcen[BB*SS];
__device__           int   g_idx[MM];
__device__ __align__(16) float g_gxyz[(size_t)MM*3];
__device__           float g_maxy[(size_t)BB*SS*128];
__device__           float g_miny[(size_t)BB*SS*128];
__device__           float g_cA[3*128];
__device__           float g_cC[3*128];
__device__           float g_dwk[128];
__device__           float g_meand;

#define PACKX2(o, lo, hi)  asm("mov.b64 %0, {%1, %2};" : "=l"(o) : "f"(lo), "f"(hi))
#define UNPACKX2(lo, hi, i) asm("mov.b64 {%0, %1}, %2;" : "=f"(lo), "=f"(hi) : "l"(i))
#define ADDX2(o, a, b) asm("add.rn.f32x2 %0, %1, %2;" : "=l"(o) : "l"(a), "l"(b))
#define MULX2(o, a, b) asm("mul.rn.f32x2 %0, %1, %2;" : "=l"(o) : "l"(a), "l"(b))

__device__ __forceinline__ unsigned f2ord(float f) {
    unsigned u = __float_as_uint(f);
    return (u & 0x80000000u) ? ~u : (u | 0x80000000u);
}
__device__ __forceinline__ float ord2f(unsigned u) {
    unsigned b = (u & 0x80000000u) ? (u ^ 0x80000000u) : ~u;
    return __uint_as_float(b);
}

// ---------------------------------------------------------------------------
// 1. FPS: 512 threads, 8 pts/thread, packed f32x2 updates (bit-identical to
//    scalar sub/mul/add). Single-barrier argmax: warp leaders atomicMax a
//    packed (val, 4096-idx) u64 into a double-buffered smem slot.
// ---------------------------------------------------------------------------
__global__ __launch_bounds__(512)
void fps_kernel(const float* __restrict__ xyz, const float* __restrict__ density,
                float* __restrict__ outxyz)
{
    extern __shared__ float smf[];
    float* sx = smf; float* sy = smf + 4096; float* sz = smf + 8192;
    int*   shist = (int*)(smf + 12288);                         // 1024
    unsigned long long* spack = (unsigned long long*)(smf + 13312);  // 2 (8B aligned)

    int b = blockIdx.x, t = threadIdx.x;
    const unsigned F = 0xffffffffu;
    const float* P = xyz + (size_t)b * NN * 3;

    // Load 8 contiguous points (24 floats = 6 float4) into registers.
    float4 f[6];
    const float4* Pv = reinterpret_cast<const float4*>(P) + t * 6;
#pragma unroll
    for (int r = 0; r < 6; r++) f[r] = Pv[r];
    const float* ff = reinterpret_cast<const float*>(f);
    float xs_[8], ys_[8], zs_[8], dist[8];
#pragma unroll
    for (int i = 0; i < 8; i++) {
        xs_[i] = ff[3*i]; ys_[i] = ff[3*i+1]; zs_[i] = ff[3*i+2];
        dist[i] = 1e10f;
        sx[t*8 + i] = xs_[i]; sy[t*8 + i] = ys_[i]; sz[t*8 + i] = zs_[i];
    }
    unsigned long long pxp[4], pyp[4], pzp[4];
#pragma unroll
    for (int j = 0; j < 4; j++) {
        PACKX2(pxp[j], xs_[2*j], xs_[2*j+1]);
        PACKX2(pyp[j], ys_[2*j], ys_[2*j+1]);
        PACKX2(pzp[j], zs_[2*j], zs_[2*j+1]);
    }
    if (t == 0) { spack[0] = 0ull; spack[1] = 0ull; }
    __syncthreads();

    int lane = t & 31;
    int far = 0;
    for (int it = 0; it < 1024; it++) {
        if (t == 0) shist[it] = far;
        float cx = sx[far], cy = sy[far], cz = sz[far];
        float ncx = -cx, ncy = -cy, ncz = -cz;
        unsigned long long cxp, cyp, czp;
        PACKX2(cxp, ncx, ncx); PACKX2(cyp, ncy, ncy); PACKX2(czp, ncz, ncz);
        float mv = -1.0f;
#pragma unroll
        for (int j = 0; j < 4; j++) {
            unsigned long long dx, dy, dz, xx, yy, zz, s1, s2;
            ADDX2(dx, pxp[j], cxp);            // px - cx (exact: a + (-b))
            ADDX2(dy, pyp[j], cyp);
            ADDX2(dz, pzp[j], czp);
            MULX2(xx, dx, dx);
            MULX2(yy, dy, dy);
            MULX2(zz, dz, dz);
            ADDX2(s1, xx, yy);
            ADDX2(s2, s1, zz);                 // ((dx^2+dy^2)+dz^2) per lane
            float d0, d1; UNPACKX2(d0, d1, s2);
            float n0 = fminf(dist[2*j],   d0);
            float n1 = fminf(dist[2*j+1], d1);
            dist[2*j] = n0; dist[2*j+1] = n1;
            mv = fmaxf(mv, fmaxf(n0, n1));
        }
        // single-barrier argmax: (max val, then lowest idx) via packed atomicMax
        unsigned vb = __float_as_uint(mv);                 // dist>=0: monotone bits
        unsigned um = __reduce_max_sync(F, vb);
        unsigned cnd = 0;
        if (vb == um) {                                    // ~1 lane per warp
            float bmf = __uint_as_float(um);
            int lj = 7;
#pragma unroll
            for (int j = 6; j >= 0; j--) if (dist[j] == bmf) lj = j;   // lowest j
            cnd = 4096u - (unsigned)(t * 8 + lj);          // larger = lower idx
        }
        unsigned mix = __reduce_max_sync(F, cnd);
        if (lane == 0)
            atomicMax(&spack[it & 1], ((unsigned long long)um << 32) | mix);
        if (t == 0) spack[(it + 1) & 1] = 0ull;            // reset other buffer
        __syncthreads();
        unsigned long long pk = spack[it & 1];
        far = 4096 - (int)(unsigned)(pk & 0xFFFFFFFFu);
    }
    __syncthreads();
    for (int s = t; s < SS; s += 512) {
        int fr = shist[s];
        float cx = sx[fr], cy = sy[fr], cz = sz[fr];
        int pidx = b * SS + s;
        outxyz[pidx*3+0] = cx; outxyz[pidx*3+1] = cy; outxyz[pidx*3+2] = cz;
        float cn = __fadd_rn(__fadd_rn(__fmul_rn(cx,cx), __fmul_rn(cy,cy)), __fmul_rn(cz,cz));
        g_c4[pidx] = make_float4(cx, cy, cz, cn);
        g_dcen[pidx] = density[b * NN + fr];
    }
}

// ---------------------------------------------------------------------------
// 1b. Pack points as (x,y,z,|p|^2)
// ---------------------------------------------------------------------------
__global__ __launch_bounds__(256)
void pts4_kernel(const float* __restrict__ xyz)
{
    int i = blockIdx.x * 256 + threadIdx.x;
    float x = xyz[i*3+0], y = xyz[i*3+1], z = xyz[i*3+2];
    float pn = __fadd_rn(__fadd_rn(__fmul_rn(x,x), __fmul_rn(y,y)), __fmul_rn(z,z));
    g_pts4[i] = make_float4(x, y, z, pn);
}

// ---------------------------------------------------------------------------
// 2. Ppre[b][n][o] = W0[o][3:].points[b][:,n] + b0[o]
// ---------------------------------------------------------------------------
__global__ __launch_bounds__(256)
void ppre_kernel(const float* __restrict__ points, const float* __restrict__ w0,
                 const float* __restrict__ b0, int boff)
{
    int blk = blockIdx.x + boff;
    int bb = blk >> 5;
    int n0 = (blk & 31) * 128;
    __shared__ __align__(16) float pts[64 * 128];
    __shared__ __align__(16) float wsm[64 * 64];
    int tid = threadIdx.x;
    const float4* src = reinterpret_cast<const float4*>(points + (size_t)bb * 64 * NN);
#pragma unroll
    for (int r = 0; r < 8; r++) {
        int i = tid + r * 256;
        int c = i >> 5, n4 = i & 31;
        float4 v = src[c * (NN/4) + (n0 >> 2) + n4];
        *reinterpret_cast<float4*>(&pts[c * 128 + n4 * 4]) = v;
    }
    for (int i = tid; i < 64 * 64; i += 256) {
        int o = i >> 6, c = i & 63;
        wsm[c * 64 + o] = w0[o * 67 + 3 + c];
    }
    __syncthreads();
    int o = tid & 63, ng = tid >> 6;
    float acc[32];
    float bo = b0[o];
#pragma unroll
    for (int j = 0; j < 32; j++) acc[j] = bo;
    for (int c = 0; c < 64; c++) {
        float w = wsm[c * 64 + o];
#pragma unroll
        for (int j = 0; j < 32; j++)
            acc[j] = fmaf(w, pts[c * 128 + ng + 4 * j], acc[j]);
    }
    float* dst = g_ppre + ((size_t)bb * NN + n0) * 64;
#pragma unroll
    for (int j = 0; j < 32; j++)
        dst[(ng + 4 * j) * 64 + o] = acc[j];
}

// ---------------------------------------------------------------------------
// 3. kNN top-32: one warp/center, FMA-form distances, 128-pt fast path.
// ---------------------------------------------------------------------------
__global__ __launch_bounds__(256)
void knn_kernel()
{
    const unsigned F = 0xffffffffu;
    int gw   = (blockIdx.x * 256 + threadIdx.x) >> 5;
    int lane = threadIdx.x & 31;
    const float4* P4 = g_pts4 + (size_t)(gw >> 10) * NN;
    float4 c = g_c4[gw];
    float nx = -2.0f * c.x, ny = -2.0f * c.y, nz = -2.0f * c.z;

    float4 p = P4[lane];
    float bv = fmaf(nx, p.x, fmaf(ny, p.y, fmaf(nz, p.z, c.w + p.w)));
    int   bi = lane;
    float Mf = ord2f(__reduce_max_sync(F, f2ord(bv)));

    auto insert_chunk = [&](float d, int base) {
        unsigned mask = __ballot_sync(F, d < Mf);
        while (mask) {
            int src = __ffs(mask) - 1;
            mask &= mask - 1;
            float dc = __shfl_sync(F, d, src);
            unsigned ub = f2ord(bv);
            unsigned mv = __reduce_max_sync(F, ub);
            float mvf = ord2f(mv);
            if (dc < mvf) {                        // strict < : top_k stable ties
                unsigned cnd = (ub == mv) ? (unsigned)(bi + 1) : 0u;   // evict max idx
                unsigned mxi = __reduce_max_sync(F, cnd);
                if (cnd == mxi && cnd) { bv = dc; bi = base + src; }
            }
            Mf = mvf;
            mask &= __ballot_sync(F, d < Mf);
        }
    };

#pragma unroll
    for (int base = 32; base < 128; base += 32) {
        p = P4[base + lane];
        float d = fmaf(nx, p.x, fmaf(ny, p.y, fmaf(nz, p.z, c.w + p.w)));
        insert_chunk(d, base);
    }
    for (int base = 128; base < NN; base += 128) {
        float d[4];
#pragma unroll
        for (int j = 0; j < 4; j++) {
            float4 q = P4[base + 32*j + lane];
            d[j] = fmaf(nx, q.x, fmaf(ny, q.y, fmaf(nz, q.z, c.w + q.w)));
        }
        float dmin = fminf(fminf(d[0], d[1]), fminf(d[2], d[3]));
        if (__ballot_sync(F, dmin < Mf) == 0u) continue;
#pragma unroll
        for (int j = 0; j < 4; j++)
            insert_chunk(d[j], base + 32*j);
    }
    g_idx[gw * NS + lane] = bi;
    float4 q = P4[bi];
    size_t gp = ((size_t)gw * NS + lane) * 3;
    g_gxyz[gp+0] = __fsub_rn(q.x, c.x);
    g_gxyz[gp+1] = __fsub_rn(q.y, c.y);
    g_gxyz[gp+2] = __fsub_rn(q.z, c.z);
}

// ---------------------------------------------------------------------------
// 4. Layer 0: gather Ppre + W0[:,0:3].gxyz; per-block BN partials.
// ---------------------------------------------------------------------------
__global__ __launch_bounds__(256)
void l0_kernel(const float* __restrict__ w0)
{
    int m0 = blockIdx.x * 64;
    int b  = m0 >> 15;
    __shared__ float sg3[64 * 3];
    __shared__ int   sid[64];
    __shared__ float red[2][64][4];
    int tid = threadIdx.x;
    if (tid < 64)  sid[tid] = g_idx[m0 + tid];
    if (tid < 192) sg3[tid] = g_gxyz[(size_t)m0 * 3 + tid];
    __syncthreads();
    int o = tid & 63, sy = tid >> 6;
    float wx = w0[o*67+0], wy = w0[o*67+1], wz = w0[o*67+2];
    const float* pp = g_ppre + (size_t)b * NN * 64;
    float s = 0.f, sq = 0.f;
#pragma unroll 4
    for (int i = 0; i < 16; i++) {
        int sl = sy + 4 * i;
        int n = sid[sl];
        float yv = __ldg(&pp[(size_t)n * 64 + o]);
        yv = fmaf(wx, sg3[sl*3+0], yv);
        yv = fmaf(wy, sg3[sl*3+1], yv);
        yv = fmaf(wz, sg3[sl*3+2], yv);
        g_y0[(size_t)(m0 + sl) * 64 + o] = yv;
        s += yv; sq += yv * yv;
    }
    red[0][o][sy] = s; red[1][o][sy] = sq;
    __syncthreads();
    if (sy == 0) {
        float S = red[0][o][0] + red[0][o][1] + red[0][o][2] + red[0][o][3];
        float Q = red[1][o][0] + red[1][o][1] + red[1][o][2] + red[1][o][3];
        g_part[(blockIdx.x * 2 + 0) * 128 + o] = S;
        g_part[(blockIdx.x * 2 + 1) * 128 + o] = Q;
    }
}

// ---------------------------------------------------------------------------
// 5. Stats partials -> per-channel (a, c)
// ---------------------------------------------------------------------------
__global__ void reduce_coef(int nblk, int layer,
                            const float* __restrict__ g, const float* __restrict__ be,
                            double invM)
{
    int o = blockIdx.x, tid = threadIdx.x;
    __shared__ double sS[256], sQ[256];
    double s = 0.0, q = 0.0;
    for (int i = tid; i < nblk; i += 256) {
        s += (double)g_part[(i*2+0)*128 + o];
        q += (double)g_part[(i*2+1)*128 + o];
    }
    sS[tid] = s; sQ[tid] = q; __syncthreads();
    for (int off = 128; off > 0; off >>= 1) {
        if (tid < off) { sS[tid] += sS[tid+off]; sQ[tid] += sQ[tid+off]; }
        __syncthreads();
    }
    if (tid == 0) {
        double mean = sS[0] * invM;
        double var  = sQ[0] * invM - mean * mean;
        double a = (double)g[o] * rsqrt(var + EPSF);
        g_cA[layer*128 + o] = (float)a;
        g_cC[layer*128 + o] = (float)((double)be[o] - mean * a);
    }
}

// ---------------------------------------------------------------------------
// 6. GEMM layers 1 & 2: packed fma.rn.f32x2, fused BN/ReLU on load,
//    stats on store; layer 2 fuses per-center max/min epilogue.
// ---------------------------------------------------------------------------
template<int NOUT, int CH, int LIN>
__global__ __launch_bounds__(256, 1)
void l12_kernel(const float* __restrict__ W, const float* __restrict__ bias)
{
    const float* yin = (LIN == 0) ? g_y0 : g_y1;
    const float* cA = g_cA + LIN * 128;
    const float* cC = g_cC + LIN * 128;
    extern __shared__ float sm[];
    float* xs = sm;                                               // [128][66]
    unsigned long long* ws = (unsigned long long*)(sm + 128*66);  // [32][NOUT+1]
    int tid = threadIdx.x, m0 = blockIdx.x * 128;

    const float4* yin4 = reinterpret_cast<const float4*>(yin + (size_t)m0 * 64);
#pragma unroll
    for (int r = 0; r < 8; r++) {
        int i = tid + r * 256, smp = i >> 4, c4 = (i & 15) * 4;
        float4 v = yin4[i];
        float* row = xs + smp * 66;
        row[c4+0] = fmaxf(0.f, fmaf(cA[c4+0], v.x, cC[c4+0]));
        row[c4+1] = fmaxf(0.f, fmaf(cA[c4+1], v.y, cC[c4+1]));
        row[c4+2] = fmaxf(0.f, fmaf(cA[c4+2], v.z, cC[c4+2]));
        row[c4+3] = fmaxf(0.f, fmaf(cA[c4+3], v.w, cC[c4+3]));
    }
    for (int i = tid; i < NOUT * 32; i += 256) {
        int k2 = i & 31, o = i >> 5;
        float2 w2 = *reinterpret_cast<const float2*>(W + o * 64 + 2 * k2);
        unsigned long long pk;
        PACKX2(pk, w2.x, w2.y);
        ws[k2 * (NOUT + 1) + o] = pk;
    }
    __syncthreads();

    int sg = tid & 15, cg = tid >> 4, obase = cg * CH;
    unsigned long long acc[8][CH];
#pragma unroll
    for (int j = 0; j < 8; j++)
#pragma unroll
        for (int q = 0; q < CH; q++)
            PACKX2(acc[j][q], bias[obase+q], 0.0f);
#pragma unroll 2
    for (int k2 = 0; k2 < 32; k2++) {
        unsigned long long xp[8];
#pragma unroll
        for (int j = 0; j < 8; j++)
            xp[j] = *reinterpret_cast<const unsigned long long*>(&xs[(sg + 16*j) * 66 + 2*k2]);
        unsigned long long wp[CH];
#pragma unroll
        for (int q = 0; q < CH; q++) wp[q] = ws[k2 * (NOUT + 1) + obase + q];
#pragma unroll
        for (int j = 0; j < 8; j++)
#pragma unroll
            for (int q = 0; q < CH; q++)
                asm("fma.rn.f32x2 %0, %1, %2, %0;" : "+l"(acc[j][q]) : "l"(xp[j]), "l"(wp[q]));
    }

    float res[8][CH];
#pragma unroll
    for (int j = 0; j < 8; j++)
#pragma unroll
        for (int q = 0; q < CH; q++) {
            float lo, hi;
            UNPACKX2(lo, hi, acc[j][q]);
            res[j][q] = lo + hi;
        }

    if constexpr (NOUT == 64) {
#pragma unroll
        for (int j = 0; j < 8; j++) {
            int m = m0 + sg + 16 * j;
            float4 v = make_float4(res[j][0], res[j][1], res[j][2], res[j][3]);
            *reinterpret_cast<float4*>(&g_y1[(size_t)m * 64 + obase]) = v;
        }
    } else {
        __syncthreads();
        float* rmx = sm;                   // [4][128][16]
        float* rmn = sm + 4 * 128 * 16;
#pragma unroll
        for (int cc = 0; cc < 4; cc++)
#pragma unroll
            for (int q = 0; q < CH; q++) {
                float a0 = res[2*cc][q], a1 = res[2*cc+1][q];
                rmx[(cc * 128 + obase + q) * 16 + sg] = fmaxf(a0, a1);
                rmn[(cc * 128 + obase + q) * 16 + sg] = fminf(a0, a1);
            }
        __syncthreads();
        for (int w = tid; w < 512; w += 256) {
            int cc = w >> 7, o = w & 127;
            float mx = -1e30f, mn = 1e30f;
#pragma unroll
            for (int i = 0; i < 16; i++) {
                mx = fmaxf(mx, rmx[(cc * 128 + o) * 16 + i]);
                mn = fminf(mn, rmn[(cc * 128 + o) * 16 + i]);
            }
            int ctr = blockIdx.x * 4 + cc;
            g_maxy[(size_t)ctr * 128 + o] = mx;
            g_miny[(size_t)ctr * 128 + o] = mn;
        }
    }

    __syncthreads();
    float* redS = sm;                      // [NOUT][16]
    float* redQ = sm + NOUT * 16;
#pragma unroll
    for (int q = 0; q < CH; q++) {
        float s = 0.f, sq = 0.f;
#pragma unroll
        for (int j = 0; j < 8; j++) { float v = res[j][q]; s += v; sq += v * v; }
        redS[(obase + q) * 16 + sg] = s;
        redQ[(obase + q) * 16 + sg] = sq;
    }
    __syncthreads();
    if (tid < NOUT) {
        float s = 0.f, sq = 0.f;
#pragma unroll
        for (int i = 0; i < 16; i++) { s += redS[tid*16+i]; sq += redQ[tid*16+i]; }
        g_part[(blockIdx.x*2+0)*128 + tid] = s;
        g_part[(blockIdx.x*2+1)*128 + tid] = sq;
    }
}

// ---------------------------------------------------------------------------
// 7. Density-branch stats (bd cancels in BN)
// ---------------------------------------------------------------------------
__global__ void dstats_kernel(const float* __restrict__ wd, const float* __restrict__ gd)
{
    __shared__ double sS[256], sQ[256];
    __shared__ double vds;
    int tid = threadIdx.x;
    double s = 0.0, q = 0.0;
    for (int i = tid; i < BB*SS; i += 256) { double v = g_dcen[i]; s += v; q += v * v; }
    sS[tid] = s; sQ[tid] = q; __syncthreads();
    for (int off = 128; off > 0; off >>= 1) {
        if (tid < off) { sS[tid] += sS[tid+off]; sQ[tid] += sQ[tid+off]; }
        __syncthreads();
    }
    if (tid == 0) {
        double md = sS[0] / (double)(BB*SS);
        vds = sQ[0] / (double)(BB*SS) - md * md;
        g_meand = (float)md;
    }
    __syncthreads();
    if (tid < 128) {
        double w = (double)wd[tid];
        g_dwk[tid] = (float)((double)gd[tid] * w * rsqrt(w * w * vds + EPSF));
    }
}

// ---------------------------------------------------------------------------
// 8. Final: out = dw * relu(a2*(a2>=0 ? maxy : miny) + c2)
// ---------------------------------------------------------------------------
__global__ __launch_bounds__(128)
void final_kernel(const float* __restrict__ bed, float* __restrict__ out)
{
    int bs = blockIdx.x, o = threadIdx.x;
    float dcen = g_dcen[bs];
    float dw = fmaxf(0.f, fmaf(g_dwk[o], dcen - g_meand, bed[o]));
    float a = g_cA[2*128 + o], c = g_cC[2*128 + o];
    float y = (a >= 0.f) ? g_maxy[(size_t)bs * 128 + o] : g_miny[(size_t)bs * 128 + o];
    float m = fmaxf(0.f, fmaf(a, y, c));
    int b = bs >> 10, s = bs & 1023;
    out[BB*SS*3 + ((size_t)(b*128 + o)) * SS + s] = m * dw;
}

// ---------------------------------------------------------------------------
extern "C" void kernel_launch(void* const* d_in, const int* in_sizes, int n_in,
                              void* d_out, int out_size)
{
    (void)in_sizes; (void)n_in; (void)out_size;
    const float* xyz     = (const float*)d_in[0];
    const float* points  = (const float*)d_in[1];
    const float* density = (const float*)d_in[2];
    const float* w0  = (const float*)d_in[3];
    const float* b0  = (const float*)d_in[4];
    const float* g0  = (const float*)d_in[5];
    const float* be0 = (const float*)d_in[6];
    const float* w1  = (const float*)d_in[7];
    const float* b1  = (const float*)d_in[8];
    const float* g1  = (const float*)d_in[9];
    const float* be1 = (const float*)d_in[10];
    const float* w2  = (const float*)d_in[11];
    const float* b2  = (const float*)d_in[12];
    const float* g2  = (const float*)d_in[13];
    const float* be2 = (const float*)d_in[14];
    const float* wd  = (const float*)d_in[15];
    const float* gd  = (const float*)d_in[17];
    const float* bed = (const float*)d_in[18];
    float* out = (float*)d_out;

    const int fps_smem = 13312*4 + 16 + 1024*4;                          // 57360
    const int smem64   = 128*66*4 + 32*65*8;                             // 50432
    const int smem128  = 128*66*4 + 32*129*8;                            // 66816
    cudaFuncSetAttribute(fps_kernel, cudaFuncAttributeMaxDynamicSharedMemorySize, fps_smem);
    cudaFuncSetAttribute(l12_kernel<64,4,0>,  cudaFuncAttributeMaxDynamicSharedMemorySize, smem64);
    cudaFuncSetAttribute(l12_kernel<128,8,1>, cudaFuncAttributeMaxDynamicSharedMemorySize, smem128);

    static cudaStream_t s_side = nullptr;
    static cudaEvent_t  e_fork = nullptr, e_join = nullptr, e_fps = nullptr, e_dst = nullptr;
    if (s_side == nullptr) {
        cudaStreamCreateWithFlags(&s_side, cudaStreamNonBlocking);
        cudaEventCreateWithFlags(&e_fork, cudaEventDisableTiming);
        cudaEventCreateWithFlags(&e_join, cudaEventDisableTiming);
        cudaEventCreateWithFlags(&e_fps,  cudaEventDisableTiming);
        cudaEventCreateWithFlags(&e_dst,  cudaEventDisableTiming);
    }

    const double invM = 1.0 / (double)MM;

    // fork: ppre + pts4 (independent of fps) run on the side stream
    cudaEventRecord(e_fork, 0);
    cudaStreamWaitEvent(s_side, e_fork, 0);
    ppre_kernel<<<256, 256, 0, s_side>>>(points, w0, b0, 0);
    ppre_kernel<<<256, 256, 0, s_side>>>(points, w0, b0, 256);
    pts4_kernel<<<BB*NN/256, 256, 0, s_side>>>(xyz);
    cudaEventRecord(e_join, s_side);

    fps_kernel <<<BB, 512, fps_smem>>>(xyz, density, out);
    cudaEventRecord(e_fps, 0);

    // side: dstats (needs only g_dcen from fps) overlaps kNN
    cudaStreamWaitEvent(s_side, e_fps, 0);
    dstats_kernel<<<1, 256, 0, s_side>>>(wd, gd);
    cudaEventRecord(e_dst, s_side);

    // join: knn needs pts4(+fps); l0 needs ppre
    cudaStreamWaitEvent(0, e_join, 0);

    knn_kernel <<<(BB*SS)/8, 256>>>();
    l0_kernel  <<<MM/64, 256>>>(w0);
    reduce_coef<<<64, 256>>>(MM/64, 0, g0, be0, invM);
    l12_kernel<64,4,0>  <<<MM/128, 256, smem64>>>(w1, b1);
    reduce_coef<<<64, 256>>>(MM/128, 1, g1, be1, invM);
    l12_kernel<128,8,1> <<<MM/128, 256, smem128>>>(w2, b2);
    reduce_coef<<<128, 256>>>(MM/128, 2, g2, be2, invM);
    cudaStreamWaitEvent(0, e_dst, 0);
    final_kernel<<<BB*SS, 128>>>(bed, out);
}

// round 14
// speedup vs baseline: 1.2077x; 1.2077x over previous
#include <cuda_runtime.h>
#include <cuda_bf16.h>

#define BB     16
#define NN     4096
#define SS     1024
#define NS     32
#define MM     (BB*SS*NS)
#define EPSF   1e-5

__device__ __align__(16) float  g_ppre[(size_t)BB*NN*64];
__device__ __align__(16) float  g_y0[(size_t)MM*64];
__device__ __align__(16) float  g_y1[(size_t)MM*64];
__device__ __align__(16) float4 g_pts4[(size_t)BB*NN];
__device__ __align__(16) float4 g_c4[BB*SS];
__device__           float g_part[8192*2*128];
__device__           float g_dcen[BB*SS];
__device__           int   g_idx[MM];
__device__ __align__(16) float g_gxyz[(size_t)MM*3];
__device__           float g_maxy[(size_t)BB*SS*128];
__device__           float g_miny[(size_t)BB*SS*128];
__device__           float g_cA[3*128];
__device__           float g_cC[3*128];
__device__           float g_dwk[128];
__device__           float g_meand;

#define PACKX2(o, lo, hi)  asm("mov.b64 %0, {%1, %2};" : "=l"(o) : "f"(lo), "f"(hi))
#define UNPACKX2(lo, hi, i) asm("mov.b64 {%0, %1}, %2;" : "=f"(lo), "=f"(hi) : "l"(i))
#define ADDX2(o, a, b) asm("add.rn.f32x2 %0, %1, %2;" : "=l"(o) : "l"(a), "l"(b))
#define MULX2(o, a, b) asm("mul.rn.f32x2 %0, %1, %2;" : "=l"(o) : "l"(a), "l"(b))

__device__ __forceinline__ unsigned f2ord(float f) {
    unsigned u = __float_as_uint(f);
    return (u & 0x80000000u) ? ~u : (u | 0x80000000u);
}
__device__ __forceinline__ float ord2f(unsigned u) {
    unsigned b = (u & 0x80000000u) ? (u ^ 0x80000000u) : ~u;
    return __uint_as_float(b);
}

// ---------------------------------------------------------------------------
// 1. FPS: 512 threads, 8 pts/thread, packed f32x2 updates (bit-identical to
//    scalar sub/mul/add). ONE-barrier argmax: warp leaders STS.64 a packed
//    (val, 4096-idx) into a double-buffered 16-slot array; all warps
//    redundantly redux the 16 winners. No atomics.
// ---------------------------------------------------------------------------
__global__ __launch_bounds__(512)
void fps_kernel(const float* __restrict__ xyz, const float* __restrict__ density,
                float* __restrict__ outxyz)
{
    extern __shared__ float smf[];
    float* sx = smf; float* sy = smf + 4096; float* sz = smf + 8192;
    int*   shist = (int*)(smf + 12288);                              // 1024
    unsigned long long* wv = (unsigned long long*)(smf + 13312);     // 2*16 (8B aligned)

    int b = blockIdx.x, t = threadIdx.x;
    const unsigned F = 0xffffffffu;
    const float* P = xyz + (size_t)b * NN * 3;

    // Load 8 contiguous points (24 floats = 6 float4) into registers.
    float4 f[6];
    const float4* Pv = reinterpret_cast<const float4*>(P) + t * 6;
#pragma unroll
    for (int r = 0; r < 6; r++) f[r] = Pv[r];
    const float* ff = reinterpret_cast<const float*>(f);
    float xs_[8], ys_[8], zs_[8], dist[8];
#pragma unroll
    for (int i = 0; i < 8; i++) {
        xs_[i] = ff[3*i]; ys_[i] = ff[3*i+1]; zs_[i] = ff[3*i+2];
        dist[i] = 1e10f;
        sx[t*8 + i] = xs_[i]; sy[t*8 + i] = ys_[i]; sz[t*8 + i] = zs_[i];
    }
    unsigned long long pxp[4], pyp[4], pzp[4];
#pragma unroll
    for (int j = 0; j < 4; j++) {
        PACKX2(pxp[j], xs_[2*j], xs_[2*j+1]);
        PACKX2(pyp[j], ys_[2*j], ys_[2*j+1]);
        PACKX2(pzp[j], zs_[2*j], zs_[2*j+1]);
    }
    __syncthreads();

    int lane = t & 31, warp = t >> 5;
    int far = 0;
    for (int it = 0; it < 1024; it++) {
        if (t == 0) shist[it] = far;
        float cx = sx[far], cy = sy[far], cz = sz[far];
        float ncx = -cx, ncy = -cy, ncz = -cz;
        unsigned long long cxp, cyp, czp;
        PACKX2(cxp, ncx, ncx); PACKX2(cyp, ncy, ncy); PACKX2(czp, ncz, ncz);
        float mv = -1.0f;
#pragma unroll
        for (int j = 0; j < 4; j++) {
            unsigned long long dx, dy, dz, xx, yy, zz, s1, s2;
            ADDX2(dx, pxp[j], cxp);            // px - cx (exact: a + (-b))
            ADDX2(dy, pyp[j], cyp);
            ADDX2(dz, pzp[j], czp);
            MULX2(xx, dx, dx);
            MULX2(yy, dy, dy);
            MULX2(zz, dz, dz);
            ADDX2(s1, xx, yy);
            ADDX2(s2, s1, zz);                 // ((dx^2+dy^2)+dz^2) per lane
            float d0, d1; UNPACKX2(d0, d1, s2);
            float n0 = fminf(dist[2*j],   d0);
            float n1 = fminf(dist[2*j+1], d1);
            dist[2*j] = n0; dist[2*j+1] = n1;
            mv = fmaxf(mv, fmaxf(n0, n1));
        }
        // warp-level: (max val, lowest idx) packed
        unsigned vb = __float_as_uint(mv);                 // dist>=0: monotone bits
        unsigned um = __reduce_max_sync(F, vb);
        unsigned cnd = 0;
        if (vb == um) {                                    // ~1 lane per warp
            float bmf = __uint_as_float(um);
            int lj = 7;
#pragma unroll
            for (int j = 6; j >= 0; j--) if (dist[j] == bmf) lj = j;   // lowest j
            cnd = 4096u - (unsigned)(t * 8 + lj);          // larger = lower idx
        }
        unsigned mix = __reduce_max_sync(F, cnd);
        if (lane == 0)
            wv[(it & 1) * 16 + warp] = ((unsigned long long)um << 32) | mix;
        __syncthreads();
        // block-level: every warp redundantly reduces the 16 warp winners
        unsigned long long pk = wv[(it & 1) * 16 + (lane & 15)];
        unsigned vb2 = (unsigned)(pk >> 32);
        unsigned m2  = __reduce_max_sync(F, vb2);
        unsigned c2  = (vb2 == m2) ? (unsigned)pk : 0u;
        unsigned mx2 = __reduce_max_sync(F, c2);
        far = 4096 - (int)mx2;
    }
    __syncthreads();
    for (int s = t; s < SS; s += 512) {
        int fr = shist[s];
        float cx = sx[fr], cy = sy[fr], cz = sz[fr];
        int pidx = b * SS + s;
        outxyz[pidx*3+0] = cx; outxyz[pidx*3+1] = cy; outxyz[pidx*3+2] = cz;
        float cn = __fadd_rn(__fadd_rn(__fmul_rn(cx,cx), __fmul_rn(cy,cy)), __fmul_rn(cz,cz));
        g_c4[pidx] = make_float4(cx, cy, cz, cn);
        g_dcen[pidx] = density[b * NN + fr];
    }
}

// ---------------------------------------------------------------------------
// 1b. Pack points as (x,y,z,|p|^2)
// ---------------------------------------------------------------------------
__global__ __launch_bounds__(256)
void pts4_kernel(const float* __restrict__ xyz)
{
    int i = blockIdx.x * 256 + threadIdx.x;
    float x = xyz[i*3+0], y = xyz[i*3+1], z = xyz[i*3+2];
    float pn = __fadd_rn(__fadd_rn(__fmul_rn(x,x), __fmul_rn(y,y)), __fmul_rn(z,z));
    g_pts4[i] = make_float4(x, y, z, pn);
}

// ---------------------------------------------------------------------------
// 2. Ppre[b][n][o] = W0[o][3:].points[b][:,n] + b0[o]
// ---------------------------------------------------------------------------
__global__ __launch_bounds__(256)
void ppre_kernel(const float* __restrict__ points, const float* __restrict__ w0,
                 const float* __restrict__ b0, int boff)
{
    int blk = blockIdx.x + boff;
    int bb = blk >> 5;
    int n0 = (blk & 31) * 128;
    __shared__ __align__(16) float pts[64 * 128];
    __shared__ __align__(16) float wsm[64 * 64];
    int tid = threadIdx.x;
    const float4* src = reinterpret_cast<const float4*>(points + (size_t)bb * 64 * NN);
#pragma unroll
    for (int r = 0; r < 8; r++) {
        int i = tid + r * 256;
        int c = i >> 5, n4 = i & 31;
        float4 v = src[c * (NN/4) + (n0 >> 2) + n4];
        *reinterpret_cast<float4*>(&pts[c * 128 + n4 * 4]) = v;
    }
    for (int i = tid; i < 64 * 64; i += 256) {
        int o = i >> 6, c = i & 63;
        wsm[c * 64 + o] = w0[o * 67 + 3 + c];
    }
    __syncthreads();
    int o = tid & 63, ng = tid >> 6;
    float acc[32];
    float bo = b0[o];
#pragma unroll
    for (int j = 0; j < 32; j++) acc[j] = bo;
    for (int c = 0; c < 64; c++) {
        float w = wsm[c * 64 + o];
#pragma unroll
        for (int j = 0; j < 32; j++)
            acc[j] = fmaf(w, pts[c * 128 + ng + 4 * j], acc[j]);
    }
    float* dst = g_ppre + ((size_t)bb * NN + n0) * 64;
#pragma unroll
    for (int j = 0; j < 32; j++)
        dst[(ng + 4 * j) * 64 + o] = acc[j];
}

// ---------------------------------------------------------------------------
// 3. kNN top-32: one warp/center, FMA-form distances, 128-pt fast path.
// ---------------------------------------------------------------------------
__global__ __launch_bounds__(256)
void knn_kernel()
{
    const unsigned F = 0xffffffffu;
    int gw   = (blockIdx.x * 256 + threadIdx.x) >> 5;
    int lane = threadIdx.x & 31;
    const float4* P4 = g_pts4 + (size_t)(gw >> 10) * NN;
    float4 c = g_c4[gw];
    float nx = -2.0f * c.x, ny = -2.0f * c.y, nz = -2.0f * c.z;

    float4 p = P4[lane];
    float bv = fmaf(nx, p.x, fmaf(ny, p.y, fmaf(nz, p.z, c.w + p.w)));
    int   bi = lane;
    float Mf = ord2f(__reduce_max_sync(F, f2ord(bv)));

    auto insert_chunk = [&](float d, int base) {
        unsigned mask = __ballot_sync(F, d < Mf);
        while (mask) {
            int src = __ffs(mask) - 1;
            mask &= mask - 1;
            float dc = __shfl_sync(F, d, src);
            unsigned ub = f2ord(bv);
            unsigned mv = __reduce_max_sync(F, ub);
            float mvf = ord2f(mv);
            if (dc < mvf) {                        // strict < : top_k stable ties
                unsigned cnd = (ub == mv) ? (unsigned)(bi + 1) : 0u;   // evict max idx
                unsigned mxi = __reduce_max_sync(F, cnd);
                if (cnd == mxi && cnd) { bv = dc; bi = base + src; }
            }
            Mf = mvf;
            mask &= __ballot_sync(F, d < Mf);
        }
    };

#pragma unroll
    for (int base = 32; base < 128; base += 32) {
        p = P4[base + lane];
        float d = fmaf(nx, p.x, fmaf(ny, p.y, fmaf(nz, p.z, c.w + p.w)));
        insert_chunk(d, base);
    }
    for (int base = 128; base < NN; base += 128) {
        float d[4];
#pragma unroll
        for (int j = 0; j < 4; j++) {
            float4 q = P4[base + 32*j + lane];
            d[j] = fmaf(nx, q.x, fmaf(ny, q.y, fmaf(nz, q.z, c.w + q.w)));
        }
        float dmin = fminf(fminf(d[0], d[1]), fminf(d[2], d[3]));
        if (__ballot_sync(F, dmin < Mf) == 0u) continue;
#pragma unroll
        for (int j = 0; j < 4; j++)
            insert_chunk(d[j], base + 32*j);
    }
    g_idx[gw * NS + lane] = bi;
    float4 q = P4[bi];
    size_t gp = ((size_t)gw * NS + lane) * 3;
    g_gxyz[gp+0] = __fsub_rn(q.x, c.x);
    g_gxyz[gp+1] = __fsub_rn(q.y, c.y);
    g_gxyz[gp+2] = __fsub_rn(q.z, c.z);
}

// ---------------------------------------------------------------------------
// 4. Layer 0: gather Ppre + W0[:,0:3].gxyz; per-block BN partials.
// ---------------------------------------------------------------------------
__global__ __launch_bounds__(256)
void l0_kernel(const float* __restrict__ w0)
{
    int m0 = blockIdx.x * 64;
    int b  = m0 >> 15;
    __shared__ float sg3[64 * 3];
    __shared__ int   sid[64];
    __shared__ float red[2][64][4];
    int tid = threadIdx.x;
    if (tid < 64)  sid[tid] = g_idx[m0 + tid];
    if (tid < 192) sg3[tid] = g_gxyz[(size_t)m0 * 3 + tid];
    __syncthreads();
    int o = tid & 63, sy = tid >> 6;
    float wx = w0[o*67+0], wy = w0[o*67+1], wz = w0[o*67+2];
    const float* pp = g_ppre + (size_t)b * NN * 64;
    float s = 0.f, sq = 0.f;
#pragma unroll 4
    for (int i = 0; i < 16; i++) {
        int sl = sy + 4 * i;
        int n = sid[sl];
        float yv = __ldg(&pp[(size_t)n * 64 + o]);
        yv = fmaf(wx, sg3[sl*3+0], yv);
        yv = fmaf(wy, sg3[sl*3+1], yv);
        yv = fmaf(wz, sg3[sl*3+2], yv);
        g_y0[(size_t)(m0 + sl) * 64 + o] = yv;
        s += yv; sq += yv * yv;
    }
    red[0][o][sy] = s; red[1][o][sy] = sq;
    __syncthreads();
    if (sy == 0) {
        float S = red[0][o][0] + red[0][o][1] + red[0][o][2] + red[0][o][3];
        float Q = red[1][o][0] + red[1][o][1] + red[1][o][2] + red[1][o][3];
        g_part[(blockIdx.x * 2 + 0) * 128 + o] = S;
        g_part[(blockIdx.x * 2 + 1) * 128 + o] = Q;
    }
}

// ---------------------------------------------------------------------------
// 5. Stats partials -> per-channel (a, c)
// ---------------------------------------------------------------------------
__global__ void reduce_coef(int nblk, int layer,
                            const float* __restrict__ g, const float* __restrict__ be,
                            double invM)
{
    int o = blockIdx.x, tid = threadIdx.x;
    __shared__ double sS[256], sQ[256];
    double s = 0.0, q = 0.0;
    for (int i = tid; i < nblk; i += 256) {
        s += (double)g_part[(i*2+0)*128 + o];
        q += (double)g_part[(i*2+1)*128 + o];
    }
    sS[tid] = s; sQ[tid] = q; __syncthreads();
    for (int off = 128; off > 0; off >>= 1) {
        if (tid < off) { sS[tid] += sS[tid+off]; sQ[tid] += sQ[tid+off]; }
        __syncthreads();
    }
    if (tid == 0) {
        double mean = sS[0] * invM;
        double var  = sQ[0] * invM - mean * mean;
        double a = (double)g[o] * rsqrt(var + EPSF);
        g_cA[layer*128 + o] = (float)a;
        g_cC[layer*128 + o] = (float)((double)be[o] - mean * a);
    }
}

// ---------------------------------------------------------------------------
// 6. GEMM layers 1 & 2: packed fma.rn.f32x2, fused BN/ReLU on load,
//    stats on store; layer 2 fuses per-center max/min epilogue.
// ---------------------------------------------------------------------------
template<int NOUT, int CH, int LIN>
__global__ __launch_bounds__(256, 1)
void l12_kernel(const float* __restrict__ W, const float* __restrict__ bias)
{
    const float* yin = (LIN == 0) ? g_y0 : g_y1;
    const float* cA = g_cA + LIN * 128;
    const float* cC = g_cC + LIN * 128;
    extern __shared__ float sm[];
    float* xs = sm;                                               // [128][66]
    unsigned long long* ws = (unsigned long long*)(sm + 128*66);  // [32][NOUT+1]
    int tid = threadIdx.x, m0 = blockIdx.x * 128;

    const float4* yin4 = reinterpret_cast<const float4*>(yin + (size_t)m0 * 64);
#pragma unroll
    for (int r = 0; r < 8; r++) {
        int i = tid + r * 256, smp = i >> 4, c4 = (i & 15) * 4;
        float4 v = yin4[i];
        float* row = xs + smp * 66;
        row[c4+0] = fmaxf(0.f, fmaf(cA[c4+0], v.x, cC[c4+0]));
        row[c4+1] = fmaxf(0.f, fmaf(cA[c4+1], v.y, cC[c4+1]));
        row[c4+2] = fmaxf(0.f, fmaf(cA[c4+2], v.z, cC[c4+2]));
        row[c4+3] = fmaxf(0.f, fmaf(cA[c4+3], v.w, cC[c4+3]));
    }
    for (int i = tid; i < NOUT * 32; i += 256) {
        int k2 = i & 31, o = i >> 5;
        float2 w2 = *reinterpret_cast<const float2*>(W + o * 64 + 2 * k2);
        unsigned long long pk;
        PACKX2(pk, w2.x, w2.y);
        ws[k2 * (NOUT + 1) + o] = pk;
    }
    __syncthreads();

    int sg = tid & 15, cg = tid >> 4, obase = cg * CH;
    unsigned long long acc[8][CH];
#pragma unroll
    for (int j = 0; j < 8; j++)
#pragma unroll
        for (int q = 0; q < CH; q++)
            PACKX2(acc[j][q], bias[obase+q], 0.0f);
#pragma unroll 2
    for (int k2 = 0; k2 < 32; k2++) {
        unsigned long long xp[8];
#pragma unroll
        for (int j = 0; j < 8; j++)
            xp[j] = *reinterpret_cast<const unsigned long long*>(&xs[(sg + 16*j) * 66 + 2*k2]);
        unsigned long long wp[CH];
#pragma unroll
        for (int q = 0; q < CH; q++) wp[q] = ws[k2 * (NOUT + 1) + obase + q];
#pragma unroll
        for (int j = 0; j < 8; j++)
#pragma unroll
            for (int q = 0; q < CH; q++)
                asm("fma.rn.f32x2 %0, %1, %2, %0;" : "+l"(acc[j][q]) : "l"(xp[j]), "l"(wp[q]));
    }

    float res[8][CH];
#pragma unroll
    for (int j = 0; j < 8; j++)
#pragma unroll
        for (int q = 0; q < CH; q++) {
            float lo, hi;
            UNPACKX2(lo, hi, acc[j][q]);
            res[j][q] = lo + hi;
        }

    if constexpr (NOUT == 64) {
#pragma unroll
        for (int j = 0; j < 8; j++) {
            int m = m0 + sg + 16 * j;
            float4 v = make_float4(res[j][0], res[j][1], res[j][2], res[j][3]);
            *reinterpret_cast<float4*>(&g_y1[(size_t)m * 64 + obase]) = v;
        }
    } else {
        __syncthreads();
        float* rmx = sm;                   // [4][128][16]
        float* rmn = sm + 4 * 128 * 16;
#pragma unroll
        for (int cc = 0; cc < 4; cc++)
#pragma unroll
            for (int q = 0; q < CH; q++) {
                float a0 = res[2*cc][q], a1 = res[2*cc+1][q];
                rmx[(cc * 128 + obase + q) * 16 + sg] = fmaxf(a0, a1);
                rmn[(cc * 128 + obase + q) * 16 + sg] = fminf(a0, a1);
            }
        __syncthreads();
        for (int w = tid; w < 512; w += 256) {
            int cc = w >> 7, o = w & 127;
            float mx = -1e30f, mn = 1e30f;
#pragma unroll
            for (int i = 0; i < 16; i++) {
                mx = fmaxf(mx, rmx[(cc * 128 + o) * 16 + i]);
                mn = fminf(mn, rmn[(cc * 128 + o) * 16 + i]);
            }
            int ctr = blockIdx.x * 4 + cc;
            g_maxy[(size_t)ctr * 128 + o] = mx;
            g_miny[(size_t)ctr * 128 + o] = mn;
        }
    }

    __syncthreads();
    float* redS = sm;                      // [NOUT][16]
    float* redQ = sm + NOUT * 16;
#pragma unroll
    for (int q = 0; q < CH; q++) {
        float s = 0.f, sq = 0.f;
#pragma unroll
        for (int j = 0; j < 8; j++) { float v = res[j][q]; s += v; sq += v * v; }
        redS[(obase + q) * 16 + sg] = s;
        redQ[(obase + q) * 16 + sg] = sq;
    }
    __syncthreads();
    if (tid < NOUT) {
        float s = 0.f, sq = 0.f;
#pragma unroll
        for (int i = 0; i < 16; i++) { s += redS[tid*16+i]; sq += redQ[tid*16+i]; }
        g_part[(blockIdx.x*2+0)*128 + tid] = s;
        g_part[(blockIdx.x*2+1)*128 + tid] = sq;
    }
}

// ---------------------------------------------------------------------------
// 7. Density-branch stats (bd cancels in BN)
// ---------------------------------------------------------------------------
__global__ void dstats_kernel(const float* __restrict__ wd, const float* __restrict__ gd)
{
    __shared__ double sS[256], sQ[256];
    __shared__ double vds;
    int tid = threadIdx.x;
    double s = 0.0, q = 0.0;
    for (int i = tid; i < BB*SS; i += 256) { double v = g_dcen[i]; s += v; q += v * v; }
    sS[tid] = s; sQ[tid] = q; __syncthreads();
    for (int off = 128; off > 0; off >>= 1) {
        if (tid < off) { sS[tid] += sS[tid+off]; sQ[tid] += sQ[tid+off]; }
        __syncthreads();
    }
    if (tid == 0) {
        double md = sS[0] / (double)(BB*SS);
        vds = sQ[0] / (double)(BB*SS) - md * md;
        g_meand = (float)md;
    }
    __syncthreads();
    if (tid < 128) {
        double w = (double)wd[tid];
        g_dwk[tid] = (float)((double)gd[tid] * w * rsqrt(w * w * vds + EPSF));
    }
}

// ---------------------------------------------------------------------------
// 8. Final: out = dw * relu(a2*(a2>=0 ? maxy : miny) + c2)
// ---------------------------------------------------------------------------
__global__ __launch_bounds__(128)
void final_kernel(const float* __restrict__ bed, float* __restrict__ out)
{
    int bs = blockIdx.x, o = threadIdx.x;
    float dcen = g_dcen[bs];
    float dw = fmaxf(0.f, fmaf(g_dwk[o], dcen - g_meand, bed[o]));
    float a = g_cA[2*128 + o], c = g_cC[2*128 + o];
    float y = (a >= 0.f) ? g_maxy[(size_t)bs * 128 + o] : g_miny[(size_t)bs * 128 + o];
    float m = fmaxf(0.f, fmaf(a, y, c));
    int b = bs >> 10, s = bs & 1023;
    out[BB*SS*3 + ((size_t)(b*128 + o)) * SS + s] = m * dw;
}

// ---------------------------------------------------------------------------
extern "C" void kernel_launch(void* const* d_in, const int* in_sizes, int n_in,
                              void* d_out, int out_size)
{
    (void)in_sizes; (void)n_in; (void)out_size;
    const float* xyz     = (const float*)d_in[0];
    const float* points  = (const float*)d_in[1];
    const float* density = (const float*)d_in[2];
    const float* w0  = (const float*)d_in[3];
    const float* b0  = (const float*)d_in[4];
    const float* g0  = (const float*)d_in[5];
    const float* be0 = (const float*)d_in[6];
    const float* w1  = (const float*)d_in[7];
    const float* b1  = (const float*)d_in[8];
    const float* g1  = (const float*)d_in[9];
    const float* be1 = (const float*)d_in[10];
    const float* w2  = (const float*)d_in[11];
    const float* b2  = (const float*)d_in[12];
    const float* g2  = (const float*)d_in[13];
    const float* be2 = (const float*)d_in[14];
    const float* wd  = (const float*)d_in[15];
    const float* gd  = (const float*)d_in[17];
    const float* bed = (const float*)d_in[18];
    float* out = (float*)d_out;

    const int fps_smem = 13312*4 + 1024*4 + 32*8;                        // 57600
    const int smem64   = 128*66*4 + 32*65*8;                             // 50432
    const int smem128  = 128*66*4 + 32*129*8;                            // 66816
    cudaFuncSetAttribute(fps_kernel, cudaFuncAttributeMaxDynamicSharedMemorySize, fps_smem);
    cudaFuncSetAttribute(l12_kernel<64,4,0>,  cudaFuncAttributeMaxDynamicSharedMemorySize, smem64);
    cudaFuncSetAttribute(l12_kernel<128,8,1>, cudaFuncAttributeMaxDynamicSharedMemorySize, smem128);

    static cudaStream_t s_side = nullptr;
    static cudaEvent_t  e_fork = nullptr, e_join = nullptr, e_fps = nullptr, e_dst = nullptr;
    if (s_side == nullptr) {
        cudaStreamCreateWithFlags(&s_side, cudaStreamNonBlocking);
        cudaEventCreateWithFlags(&e_fork, cudaEventDisableTiming);
        cudaEventCreateWithFlags(&e_join, cudaEventDisableTiming);
        cudaEventCreateWithFlags(&e_fps,  cudaEventDisableTiming);
        cudaEventCreateWithFlags(&e_dst,  cudaEventDisableTiming);
    }

    const double invM = 1.0 / (double)MM;

    // fork: ppre + pts4 (independent of fps) run on the side stream
    cudaEventRecord(e_fork, 0);
    cudaStreamWaitEvent(s_side, e_fork, 0);
    ppre_kernel<<<256, 256, 0, s_side>>>(points, w0, b0, 0);
    ppre_kernel<<<256, 256, 0, s_side>>>(points, w0, b0, 256);
    pts4_kernel<<<BB*NN/256, 256, 0, s_side>>>(xyz);
    cudaEventRecord(e_join, s_side);

    fps_kernel <<<BB, 512, fps_smem>>>(xyz, density, out);
    cudaEventRecord(e_fps, 0);

    // side: dstats (needs only g_dcen from fps) overlaps kNN
    cudaStreamWaitEvent(s_side, e_fps, 0);
    dstats_kernel<<<1, 256, 0, s_side>>>(wd, gd);
    cudaEventRecord(e_dst, s_side);

    // join: knn needs pts4(+fps); l0 needs ppre
    cudaStreamWaitEvent(0, e_join, 0);

    knn_kernel <<<(BB*SS)/8, 256>>>();
    l0_kernel  <<<MM/64, 256>>>(w0);
    reduce_coef<<<64, 256>>>(MM/64, 0, g0, be0, invM);
    l12_kernel<64,4,0>  <<<MM/128, 256, smem64>>>(w1, b1);
    reduce_coef<<<64, 256>>>(MM/128, 1, g1, be1, invM);
    l12_kernel<128,8,1> <<<MM/128, 256, smem128>>>(w2, b2);
    reduce_coef<<<128, 256>>>(MM/128, 2, g2, be2, invM);
    cudaStreamWaitEvent(0, e_dst, 0);
    final_kernel<<<BB*SS, 128>>>(bed, out);
}